// round 13
// baseline (speedup 1.0000x reference)
#include <cuda_runtime.h>
#include <cuda_fp16.h>
#include <math.h>
#include <stdint.h>

// ---------------- problem constants ----------------
#define NT   16384
#define DM   1024
#define HS   1024
#define NSEG 4
#define KDIM 1024

#define BM   128
#define BN   256
#define BK   64
#define NKIT (KDIM / BK)        // 16
#define NTHR 256                // 8 warps: 2 wm x 4 wn, warp tile 64x64

#define MAX_ROWS (NT + NSEG * BM)   // 16896
#define MTILES   (MAX_ROWS / BM)    // 132
#define NPROD    (MTILES * 8)       // 1056 gemm1 CTAs
#define NCONS    (MTILES * 4)       // 528 gemm2 CTAs

// SMEM stage: rows of 64 fp16 = 128B data, padded to 144B (conflict-free ldmatrix)
#define ROWB     144
#define TILEA    (128 * ROWB)       // 18432
#define TILEB    (256 * ROWB)       // 36864
#define STAGEB   (TILEA + TILEB)    // 55296
#define NSTAGE   4
#define SMEM_G   (NSTAGE * STAGEB)  // 221184 (>= epilogue 137216)
#define EPI_STRIDE 268

// ---------------- device scratch ----------------
__device__ int g_perm[MAX_ROWS];
__device__ int g_count[NSEG];
__device__ int g_cursor[NSEG];
__device__ int g_off[NSEG + 1];
__device__ int g_is32;
__device__ int g_done[MTILES];

__device__ __half g_xh[(size_t)MAX_ROWS * DM];   // activations fp16
__device__ __half g_hh[(size_t)MAX_ROWS * HS];   // hidden fp16
// weights K-major [seg][n][k], fp16
__device__ __half g_wg[(size_t)NSEG * HS * DM];
__device__ __half g_wu[(size_t)NSEG * HS * DM];
__device__ __half g_wd[(size_t)NSEG * DM * HS];

// ---------------- small helpers ----------------
__device__ __forceinline__ uint32_t s2u(const void* p) {
    return (uint32_t)__cvta_generic_to_shared(p);
}
__device__ __forceinline__ void cpa16(uint32_t dst, const void* src) {
    asm volatile("cp.async.cg.shared.global [%0], [%1], 16;" :: "r"(dst), "l"(src));
}
#define CP_COMMIT() asm volatile("cp.async.commit_group;" ::: "memory")
#define CP_WAIT2()  asm volatile("cp.async.wait_group 2;" ::: "memory")
#define CP_WAIT0()  asm volatile("cp.async.wait_group 0;" ::: "memory")

__device__ __forceinline__ void ldmx4(uint32_t* r, uint32_t addr) {
    asm volatile("ldmatrix.sync.aligned.m8n8.x4.shared.b16 {%0,%1,%2,%3}, [%4];"
        : "=r"(r[0]), "=r"(r[1]), "=r"(r[2]), "=r"(r[3]) : "r"(addr));
}
__device__ __forceinline__ void mma16816(float* c, const uint32_t* a, const uint32_t* b) {
    asm volatile(
        "mma.sync.aligned.m16n8k16.row.col.f32.f16.f16.f32 "
        "{%0,%1,%2,%3}, {%4,%5,%6,%7}, {%8,%9}, {%0,%1,%2,%3};"
        : "+f"(c[0]), "+f"(c[1]), "+f"(c[2]), "+f"(c[3])
        : "r"(a[0]), "r"(a[1]), "r"(a[2]), "r"(a[3]), "r"(b[0]), "r"(b[1]));
}
__device__ __forceinline__ uint32_t packh2(__half a, __half b) {
    return ((uint32_t)__half_as_ushort(b) << 16) | __half_as_ushort(a);
}

// ---------------- routing kernels ----------------
__global__ void k_prep() {
    int i = blockIdx.x * blockDim.x + threadIdx.x;
    if (i < MAX_ROWS) g_perm[i] = -1;
    if (i < NSEG) { g_count[i] = 0; g_cursor[i] = 0; }
    if (i < MTILES) g_done[i] = 0;
    if (i == 0) g_is32 = 0;
}
__global__ void k_detect(const int* __restrict__ idx32) {
    int i = blockIdx.x * blockDim.x + threadIdx.x;
    if (i < NT / 2 && idx32[2 * i + 1] != 0) atomicExch(&g_is32, 1);
}
__device__ __forceinline__ int seg_of(const int* __restrict__ idx32, int i) {
    return (g_is32 ? idx32[i] : idx32[2 * i]) & (NSEG - 1);
}
__global__ void k_count(const int* __restrict__ idx32) {
    int i = blockIdx.x * blockDim.x + threadIdx.x;
    if (i < NT) atomicAdd(&g_count[seg_of(idx32, i)], 1);
}
__global__ void k_off() {
    if (threadIdx.x == 0 && blockIdx.x == 0) {
        int o = 0;
        for (int s = 0; s < NSEG; s++) {
            g_off[s] = o;
            o += ((g_count[s] + BM - 1) / BM) * BM;
        }
        g_off[NSEG] = o;
    }
}
__global__ void k_scatter(const int* __restrict__ idx32) {
    int i = blockIdx.x * blockDim.x + threadIdx.x;
    if (i < NT) {
        int s = seg_of(idx32, i);
        g_perm[g_off[s] + atomicAdd(&g_cursor[s], 1)] = i;
    }
}

// ---------------- conversion: gathered x -> fp16 ----------------
__global__ void k_convx(const float* __restrict__ x) {
    int gid = blockIdx.x * blockDim.x + threadIdx.x;
    if (gid >= MAX_ROWS * (DM / 4)) return;
    int r = gid >> 8;
    int c = (gid & 255) << 2;
    int t = g_perm[r];
    float4 v = (t >= 0) ? *reinterpret_cast<const float4*>(x + (size_t)t * DM + c)
                        : make_float4(0.f, 0.f, 0.f, 0.f);
    size_t o = (size_t)r * DM + c;
    *reinterpret_cast<uint2*>(g_xh + o) =
        make_uint2(packh2(__float2half(v.x), __float2half(v.y)),
                   packh2(__float2half(v.z), __float2half(v.w)));
}

// ---------------- conversion: weights fp32 [k][n] -> fp16 [n][k] ----------------
__global__ void k_convw(const float* __restrict__ gw, const float* __restrict__ uw,
                        const float* __restrict__ dw) {
    __shared__ float tile[32][33];
    int mat = blockIdx.z >> 2, seg = blockIdx.z & 3;
    const float* W = (mat == 0 ? gw : (mat == 1 ? uw : dw)) + (size_t)seg * DM * HS;
    __half* O = (mat == 0 ? g_wg : (mat == 1 ? g_wu : g_wd)) + (size_t)seg * DM * HS;
    int n0 = blockIdx.x * 32, k0 = blockIdx.y * 32;
    int tx = threadIdx.x, ty = threadIdx.y;
#pragma unroll
    for (int i = 0; i < 4; i++)
        tile[ty + 8 * i][tx] = W[(size_t)(k0 + ty + 8 * i) * 1024 + n0 + tx];
    __syncthreads();
#pragma unroll
    for (int i = 0; i < 4; i++) {
        float v = tile[tx][ty + 8 * i];
        O[(size_t)(n0 + ty + 8 * i) * 1024 + k0 + tx] = __float2half(v);
    }
}

// ---------------- stage loader (256 threads; 12 cp.async each) ----------------
__device__ __forceinline__ void ld_stage(uint32_t sb,
        const __half* gA, const __half* B0, const __half* B1,
        int kc, int tid) {
    const int ko = kc * BK;
#pragma unroll
    for (int q = 0; q < 4; q++) {               // A: 128 rows x 8 chunks
        int id = q * NTHR + tid;
        int row = id >> 3, c = id & 7;
        cpa16(sb + row * ROWB + c * 16, gA + (size_t)row * KDIM + ko + c * 8);
    }
#pragma unroll
    for (int q = 0; q < 8; q++) {               // B: 256 rows x 8 chunks
        int id = q * NTHR + tid;
        int row = id >> 3, c = id & 7;
        const __half* src = (row < 128) ? B0 : (B1 - (size_t)128 * KDIM);
        cpa16(sb + TILEA + row * ROWB + c * 16, src + (size_t)row * KDIM + ko + c * 8);
    }
}

// ---------------- GEMM mainloop: CTA 128x256, 8 warps of 64x64, 4-stage ----------------
__device__ __forceinline__ void gemm_mainloop(uint32_t sbase,
        const __half* gA, const __half* B0, const __half* B1,
        int tid, float acc[4][8][4]) {
    const int lane = tid & 31, wid = tid >> 5;
    const int wm = wid & 1, wn = wid >> 1;

#pragma unroll
    for (int i = 0; i < 4; i++)
#pragma unroll
        for (int j = 0; j < 8; j++)
#pragma unroll
            for (int q = 0; q < 4; q++) acc[i][j][q] = 0.f;

    ld_stage(sbase,              gA, B0, B1, 0, tid); CP_COMMIT();
    ld_stage(sbase + STAGEB,     gA, B0, B1, 1, tid); CP_COMMIT();
    ld_stage(sbase + 2 * STAGEB, gA, B0, B1, 2, tid); CP_COMMIT();

    const int a_r  = lane & 15;
    const int a_kb = (lane >> 4) << 4;
    const int b_r  = ((lane >> 4) << 3) + (lane & 7);
    const int b_kb = ((lane >> 3) & 1) << 4;
    const int a_row0 = wm * 64;
    const int b_col0 = wn * 64;

    for (int it = 0; it < NKIT; it++) {
        if (it + 3 < NKIT) CP_WAIT2(); else CP_WAIT0();
        __syncthreads();
        if (it + 3 < NKIT) {
            ld_stage(sbase + ((it + 3) % NSTAGE) * STAGEB, gA, B0, B1, it + 3, tid);
            CP_COMMIT();
        }
        const uint32_t sb = sbase + (it % NSTAGE) * STAGEB;
        const uint32_t sB = sb + TILEA;
#pragma unroll
        for (int ks = 0; ks < 4; ks++) {
            const int kb = ks * 32;
            uint32_t aH[4][4];
#pragma unroll
            for (int mt = 0; mt < 4; mt++) {
                uint32_t ad = sb + (a_row0 + mt * 16 + a_r) * ROWB + kb + a_kb;
                ldmx4(aH[mt], ad);
            }
#pragma unroll
            for (int nh = 0; nh < 2; nh++) {
                uint32_t bH[4][2];
#pragma unroll
                for (int p = 0; p < 2; p++) {
                    uint32_t bd = sB + (b_col0 + nh * 32 + p * 16 + b_r) * ROWB + kb + b_kb;
                    uint32_t r[4];
                    ldmx4(r, bd);
                    bH[2 * p][0] = r[0]; bH[2 * p][1] = r[1];
                    bH[2 * p + 1][0] = r[2]; bH[2 * p + 1][1] = r[3];
                }
#pragma unroll
                for (int mt = 0; mt < 4; mt++)
#pragma unroll
                    for (int q = 0; q < 4; q++)
                        mma16816(acc[mt][nh * 4 + q], aH[mt], bH[q]);
            }
        }
    }
}

// ---------------- fused GEMM kernel: producers (gemm1) + consumers (gemm2) ----------------
__global__ __launch_bounds__(NTHR, 1) void gemm_fused(float* __restrict__ out) {
    extern __shared__ char smem[];
    const int bid = blockIdx.x;
    const int tid = threadIdx.x, lane = tid & 31, wid = tid >> 5;
    const int wm = wid & 1, wn = wid >> 1;

    if (bid < NPROD) {
        // ---- producer: gemm1 [gate|up] + fused SwiGLU ----
        const int mt_idx = bid >> 3;
        const int m0 = mt_idx * BM;
        if (m0 >= g_off[NSEG]) return;
        const int h0 = (bid & 7) * 128;
        int seg = 0;
#pragma unroll
        for (int s = 1; s < NSEG; s++) if (m0 >= g_off[s]) seg = s;

        const __half* gA = g_xh + (size_t)m0 * DM;
        const size_t wo = ((size_t)seg * HS + h0) * DM;

        float acc[4][8][4];
        gemm_mainloop(s2u(smem), gA, g_wg + wo, g_wu + wo, tid, acc);

        __syncthreads();
        float* S = reinterpret_cast<float*>(smem);
#pragma unroll
        for (int mt = 0; mt < 4; mt++) {
            const int r = wm * 64 + mt * 16 + (lane >> 2);
#pragma unroll
            for (int nt = 0; nt < 8; nt++) {
                const int c = wn * 64 + nt * 8 + (lane & 3) * 2;
                *reinterpret_cast<float2*>(S + (size_t)r * EPI_STRIDE + c) =
                    make_float2(acc[mt][nt][0], acc[mt][nt][1]);
                *reinterpret_cast<float2*>(S + (size_t)(r + 8) * EPI_STRIDE + c) =
                    make_float2(acc[mt][nt][2], acc[mt][nt][3]);
            }
        }
        __syncthreads();

        // swiglu -> fp16 hidden: 256 threads, each 64 hidden cols of one row
        const int row = tid >> 1, half = tid & 1;
        const float* Sg = S + (size_t)row * EPI_STRIDE + half * 64;
        const float* Su = Sg + 128;
        __half* dh = g_hh + (size_t)(m0 + row) * HS + h0 + half * 64;
#pragma unroll
        for (int j = 0; j < 16; j++) {
            float4 gv = *reinterpret_cast<const float4*>(Sg + 4 * j);
            float4 uv = *reinterpret_cast<const float4*>(Su + 4 * j);
            float h0v = (gv.x / (1.f + __expf(-gv.x))) * uv.x;
            float h1v = (gv.y / (1.f + __expf(-gv.y))) * uv.y;
            float h2v = (gv.z / (1.f + __expf(-gv.z))) * uv.z;
            float h3v = (gv.w / (1.f + __expf(-gv.w))) * uv.w;
            *reinterpret_cast<uint2*>(dh + 4 * j) =
                make_uint2(packh2(__float2half(h0v), __float2half(h1v)),
                           packh2(__float2half(h2v), __float2half(h3v)));
        }
        __threadfence();
        __syncthreads();
        if (tid == 0) atomicAdd(&g_done[mt_idx], 1);
    } else {
        // ---- consumer: gemm2 with scatter epilogue ----
        const int c = bid - NPROD;
        const int mt_idx = c % MTILES;
        const int m0 = mt_idx * BM;
        if (m0 >= g_off[NSEG]) return;
        const int n0 = (c / MTILES) * BN;
        int seg = 0;
#pragma unroll
        for (int s = 1; s < NSEG; s++) if (m0 >= g_off[s]) seg = s;

        if (tid == 0) {
            while (atomicAdd(&g_done[mt_idx], 0) < 8) { }
        }
        __syncthreads();
        __threadfence();

        const __half* gA = g_hh + (size_t)m0 * HS;
        const size_t wo = ((size_t)seg * DM + n0) * HS;
        const __half* B = g_wd + wo;

        float acc[4][8][4];
        gemm_mainloop(s2u(smem), gA, B, B + (size_t)128 * HS, tid, acc);

#pragma unroll
        for (int mt = 0; mt < 4; mt++) {
            const int rb = m0 + wm * 64 + mt * 16 + (lane >> 2);
            const int t0 = g_perm[rb];
            const int t1 = g_perm[rb + 8];
#pragma unroll
            for (int nt = 0; nt < 8; nt++) {
                const int cc = n0 + wn * 64 + nt * 8 + (lane & 3) * 2;
                if (t0 >= 0)
                    *reinterpret_cast<float2*>(out + (size_t)t0 * DM + cc) =
                        make_float2(acc[mt][nt][0], acc[mt][nt][1]);
                if (t1 >= 0)
                    *reinterpret_cast<float2*>(out + (size_t)t1 * DM + cc) =
                        make_float2(acc[mt][nt][2], acc[mt][nt][3]);
            }
        }
    }
}

// ---------------- entry point ----------------
extern "C" void kernel_launch(void* const* d_in, const int* in_sizes, int n_in,
                              void* d_out, int out_size)
{
    const float* x   = (const float*)d_in[0];
    const float* gw  = (const float*)d_in[1];
    const float* uw  = (const float*)d_in[2];
    const float* dw  = (const float*)d_in[3];
    const int*   idx = (const int*)d_in[4];
    float* out = (float*)d_out;

    static int smem_set = 0;
    if (!smem_set) {
        cudaFuncSetAttribute(gemm_fused, cudaFuncAttributeMaxDynamicSharedMemorySize, SMEM_G);
        smem_set = 1;
    }

    k_prep<<<(MAX_ROWS + 255) / 256, 256>>>();
    k_detect<<<(NT / 2 + 255) / 256, 256>>>(idx);
    k_count<<<(NT + 255) / 256, 256>>>(idx);
    k_off<<<1, 32>>>();
    k_scatter<<<(NT + 255) / 256, 256>>>(idx);

    k_convw<<<dim3(32, 32, 12), dim3(32, 8)>>>(gw, uw, dw);
    k_convx<<<(MAX_ROWS * (DM / 4) + 255) / 256, 256>>>(x);

    gemm_fused<<<NPROD + NCONS, NTHR, SMEM_G>>>(out);
}

// round 14
// speedup vs baseline: 1.1303x; 1.1303x over previous
#include <cuda_runtime.h>
#include <cuda_fp16.h>
#include <math.h>
#include <stdint.h>

// ---------------- problem constants ----------------
#define NT   16384
#define DM   1024
#define HS   1024
#define NSEG 4
#define KDIM 1024

#define BM   128
#define BN   128
#define BK   64
#define NKIT (KDIM / BK)        // 16
#define NTHR 256                // 8 warps: 4 wm x 2 wn, warp tile 32x64

#define MAX_ROWS (NT + NSEG * BM)   // 16896
#define MTILES   (MAX_ROWS / BM)    // 132
#define NPROD    (MTILES * 16)      // 2112 gemm1 CTAs (64 hidden cols each)
#define NCONS    (MTILES * 8)       // 1056 gemm2 CTAs

// SMEM stage: rows of 64 fp16 = 128B data, padded to 144B (conflict-free ldmatrix)
// A: 128 rows; B: 128 rows.
#define ROWB     144
#define TILEA    (128 * ROWB)       // 18432
#define TILEB    (128 * ROWB)       // 18432
#define STAGEB   (TILEA + TILEB)    // 36864
#define NSTAGE   3
#define SMEM_G   (NSTAGE * STAGEB)  // 110592 -> 2 CTAs/SM
#define EPI_STRIDE 132              // fp32 epilogue smem stride (128 cols + pad)

// ---------------- device scratch ----------------
__device__ int g_perm[MAX_ROWS];
__device__ int g_count[NSEG];
__device__ int g_cursor[NSEG];
__device__ int g_off[NSEG + 1];
__device__ int g_is32;
__device__ int g_done[MTILES];

__device__ __half g_xh[(size_t)MAX_ROWS * DM];   // activations fp16
__device__ __half g_hh[(size_t)MAX_ROWS * HS];   // hidden fp16
// weights K-major [seg][n][k], fp16
__device__ __half g_wg[(size_t)NSEG * HS * DM];
__device__ __half g_wu[(size_t)NSEG * HS * DM];
__device__ __half g_wd[(size_t)NSEG * DM * HS];

// ---------------- small helpers ----------------
__device__ __forceinline__ uint32_t s2u(const void* p) {
    return (uint32_t)__cvta_generic_to_shared(p);
}
__device__ __forceinline__ void cpa16(uint32_t dst, const void* src) {
    asm volatile("cp.async.cg.shared.global [%0], [%1], 16;" :: "r"(dst), "l"(src));
}
#define CP_COMMIT() asm volatile("cp.async.commit_group;" ::: "memory")
#define CP_WAIT1()  asm volatile("cp.async.wait_group 1;" ::: "memory")
#define CP_WAIT0()  asm volatile("cp.async.wait_group 0;" ::: "memory")

__device__ __forceinline__ void ldmx4(uint32_t* r, uint32_t addr) {
    asm volatile("ldmatrix.sync.aligned.m8n8.x4.shared.b16 {%0,%1,%2,%3}, [%4];"
        : "=r"(r[0]), "=r"(r[1]), "=r"(r[2]), "=r"(r[3]) : "r"(addr));
}
__device__ __forceinline__ void mma16816(float* c, const uint32_t* a, const uint32_t* b) {
    asm volatile(
        "mma.sync.aligned.m16n8k16.row.col.f32.f16.f16.f32 "
        "{%0,%1,%2,%3}, {%4,%5,%6,%7}, {%8,%9}, {%0,%1,%2,%3};"
        : "+f"(c[0]), "+f"(c[1]), "+f"(c[2]), "+f"(c[3])
        : "r"(a[0]), "r"(a[1]), "r"(a[2]), "r"(a[3]), "r"(b[0]), "r"(b[1]));
}
__device__ __forceinline__ uint32_t packh2(__half a, __half b) {
    return ((uint32_t)__half_as_ushort(b) << 16) | __half_as_ushort(a);
}

// ---------------- routing kernels ----------------
__global__ void k_prep() {
    int i = blockIdx.x * blockDim.x + threadIdx.x;
    if (i < MAX_ROWS) g_perm[i] = -1;
    if (i < NSEG) { g_count[i] = 0; g_cursor[i] = 0; }
    if (i < MTILES) g_done[i] = 0;
    if (i == 0) g_is32 = 0;
}
__global__ void k_detect(const int* __restrict__ idx32) {
    int i = blockIdx.x * blockDim.x + threadIdx.x;
    if (i < NT / 2 && idx32[2 * i + 1] != 0) atomicExch(&g_is32, 1);
}
__device__ __forceinline__ int seg_of(const int* __restrict__ idx32, int i) {
    return (g_is32 ? idx32[i] : idx32[2 * i]) & (NSEG - 1);
}
__global__ void k_count(const int* __restrict__ idx32) {
    int i = blockIdx.x * blockDim.x + threadIdx.x;
    if (i < NT) atomicAdd(&g_count[seg_of(idx32, i)], 1);
}
__global__ void k_off() {
    if (threadIdx.x == 0 && blockIdx.x == 0) {
        int o = 0;
        for (int s = 0; s < NSEG; s++) {
            g_off[s] = o;
            o += ((g_count[s] + BM - 1) / BM) * BM;
        }
        g_off[NSEG] = o;
    }
}
__global__ void k_scatter(const int* __restrict__ idx32) {
    int i = blockIdx.x * blockDim.x + threadIdx.x;
    if (i < NT) {
        int s = seg_of(idx32, i);
        g_perm[g_off[s] + atomicAdd(&g_cursor[s], 1)] = i;
    }
}

// ---------------- conversion: gathered x -> fp16 ----------------
__global__ void k_convx(const float* __restrict__ x) {
    int gid = blockIdx.x * blockDim.x + threadIdx.x;
    if (gid >= MAX_ROWS * (DM / 4)) return;
    int r = gid >> 8;
    int c = (gid & 255) << 2;
    int t = g_perm[r];
    float4 v = (t >= 0) ? *reinterpret_cast<const float4*>(x + (size_t)t * DM + c)
                        : make_float4(0.f, 0.f, 0.f, 0.f);
    size_t o = (size_t)r * DM + c;
    *reinterpret_cast<uint2*>(g_xh + o) =
        make_uint2(packh2(__float2half(v.x), __float2half(v.y)),
                   packh2(__float2half(v.z), __float2half(v.w)));
}

// ---------------- conversion: weights fp32 [k][n] -> fp16 [n][k] ----------------
__global__ void k_convw(const float* __restrict__ gw, const float* __restrict__ uw,
                        const float* __restrict__ dw) {
    __shared__ float tile[32][33];
    int mat = blockIdx.z >> 2, seg = blockIdx.z & 3;
    const float* W = (mat == 0 ? gw : (mat == 1 ? uw : dw)) + (size_t)seg * DM * HS;
    __half* O = (mat == 0 ? g_wg : (mat == 1 ? g_wu : g_wd)) + (size_t)seg * DM * HS;
    int n0 = blockIdx.x * 32, k0 = blockIdx.y * 32;
    int tx = threadIdx.x, ty = threadIdx.y;
#pragma unroll
    for (int i = 0; i < 4; i++)
        tile[ty + 8 * i][tx] = W[(size_t)(k0 + ty + 8 * i) * 1024 + n0 + tx];
    __syncthreads();
#pragma unroll
    for (int i = 0; i < 4; i++) {
        float v = tile[tx][ty + 8 * i];
        O[(size_t)(n0 + ty + 8 * i) * 1024 + k0 + tx] = __float2half(v);
    }
}

// ---------------- stage loader (256 threads; 8 cp.async each) ----------------
// B panel: rows 0-63 from B0, rows 64-127 from B1 (B1 pre-offset by caller).
__device__ __forceinline__ void ld_stage(uint32_t sb,
        const __half* gA, const __half* B0, const __half* B1,
        int kc, int tid) {
    const int ko = kc * BK;
#pragma unroll
    for (int q = 0; q < 4; q++) {               // A: 128 rows x 8 chunks
        int id = q * NTHR + tid;
        int row = id >> 3, c = id & 7;
        cpa16(sb + row * ROWB + c * 16, gA + (size_t)row * KDIM + ko + c * 8);
    }
#pragma unroll
    for (int q = 0; q < 4; q++) {               // B: 128 rows x 8 chunks
        int id = q * NTHR + tid;
        int row = id >> 3, c = id & 7;
        const __half* src = (row < 64) ? B0 : (B1 - (size_t)64 * KDIM);
        cpa16(sb + TILEA + row * ROWB + c * 16, src + (size_t)row * KDIM + ko + c * 8);
    }
}

// ---------------- GEMM mainloop: CTA 128x128, 8 warps of 32x64, 3-stage ----------------
__device__ __forceinline__ void gemm_mainloop(uint32_t sbase,
        const __half* gA, const __half* B0, const __half* B1,
        int tid, float acc[2][8][4]) {
    const int lane = tid & 31, wid = tid >> 5;
    const int wm = wid & 3, wn = wid >> 2;

#pragma unroll
    for (int i = 0; i < 2; i++)
#pragma unroll
        for (int j = 0; j < 8; j++)
#pragma unroll
            for (int q = 0; q < 4; q++) acc[i][j][q] = 0.f;

    ld_stage(sbase,          gA, B0, B1, 0, tid); CP_COMMIT();
    ld_stage(sbase + STAGEB, gA, B0, B1, 1, tid); CP_COMMIT();

    const int a_r  = lane & 15;
    const int a_kb = (lane >> 4) << 4;
    const int b_r  = ((lane >> 4) << 3) + (lane & 7);
    const int b_kb = ((lane >> 3) & 1) << 4;
    const int a_row0 = wm * 32;
    const int b_col0 = wn * 64;

    for (int it = 0; it < NKIT; it++) {
        if (it + 2 < NKIT) CP_WAIT1(); else CP_WAIT0();
        __syncthreads();
        if (it + 2 < NKIT) {
            ld_stage(sbase + ((it + 2) % NSTAGE) * STAGEB, gA, B0, B1, it + 2, tid);
            CP_COMMIT();
        }
        const uint32_t sb = sbase + (it % NSTAGE) * STAGEB;
        const uint32_t sB = sb + TILEA;
#pragma unroll
        for (int ks = 0; ks < 4; ks++) {
            const int kb = ks * 32;
            uint32_t aH[2][4];
#pragma unroll
            for (int mt = 0; mt < 2; mt++) {
                uint32_t ad = sb + (a_row0 + mt * 16 + a_r) * ROWB + kb + a_kb;
                ldmx4(aH[mt], ad);
            }
#pragma unroll
            for (int nh = 0; nh < 2; nh++) {
                uint32_t bH[4][2];
#pragma unroll
                for (int p = 0; p < 2; p++) {
                    uint32_t bd = sB + (b_col0 + nh * 32 + p * 16 + b_r) * ROWB + kb + b_kb;
                    uint32_t r[4];
                    ldmx4(r, bd);
                    bH[2 * p][0] = r[0]; bH[2 * p][1] = r[1];
                    bH[2 * p + 1][0] = r[2]; bH[2 * p + 1][1] = r[3];
                }
#pragma unroll
                for (int mt = 0; mt < 2; mt++)
#pragma unroll
                    for (int q = 0; q < 4; q++)
                        mma16816(acc[mt][nh * 4 + q], aH[mt], bH[q]);
            }
        }
    }
}

// ---------------- fused GEMM kernel: producers (gemm1) + consumers (gemm2) ----------------
__global__ __launch_bounds__(NTHR, 2) void gemm_fused(float* __restrict__ out) {
    extern __shared__ char smem[];
    const int bid = blockIdx.x;
    const int tid = threadIdx.x, lane = tid & 31, wid = tid >> 5;
    const int wm = wid & 3, wn = wid >> 2;

    if (bid < NPROD) {
        // ---- producer: gemm1 [64 gate | 64 up] + fused SwiGLU ----
        const int mt_idx = bid >> 4;
        const int m0 = mt_idx * BM;
        if (m0 >= g_off[NSEG]) return;
        const int h0 = (bid & 15) * 64;
        int seg = 0;
#pragma unroll
        for (int s = 1; s < NSEG; s++) if (m0 >= g_off[s]) seg = s;

        const __half* gA = g_xh + (size_t)m0 * DM;
        const size_t wo = ((size_t)seg * HS + h0) * DM;

        float acc[2][8][4];
        gemm_mainloop(s2u(smem), gA, g_wg + wo, g_wu + wo, tid, acc);

        __syncthreads();
        float* S = reinterpret_cast<float*>(smem);
#pragma unroll
        for (int mt = 0; mt < 2; mt++) {
            const int r = wm * 32 + mt * 16 + (lane >> 2);
#pragma unroll
            for (int nt = 0; nt < 8; nt++) {
                const int c = wn * 64 + nt * 8 + (lane & 3) * 2;
                *reinterpret_cast<float2*>(S + (size_t)r * EPI_STRIDE + c) =
                    make_float2(acc[mt][nt][0], acc[mt][nt][1]);
                *reinterpret_cast<float2*>(S + (size_t)(r + 8) * EPI_STRIDE + c) =
                    make_float2(acc[mt][nt][2], acc[mt][nt][3]);
            }
        }
        __syncthreads();

        // swiglu -> fp16 hidden: cols 0-63 gate, 64-127 up; pair (c, c+64)
        const int row = tid >> 1, half = tid & 1;
        const float* Sg = S + (size_t)row * EPI_STRIDE + half * 32;
        const float* Su = Sg + 64;
        __half* dh = g_hh + (size_t)(m0 + row) * HS + h0 + half * 32;
#pragma unroll
        for (int j = 0; j < 8; j++) {
            float4 gv = *reinterpret_cast<const float4*>(Sg + 4 * j);
            float4 uv = *reinterpret_cast<const float4*>(Su + 4 * j);
            float h0v = (gv.x / (1.f + __expf(-gv.x))) * uv.x;
            float h1v = (gv.y / (1.f + __expf(-gv.y))) * uv.y;
            float h2v = (gv.z / (1.f + __expf(-gv.z))) * uv.z;
            float h3v = (gv.w / (1.f + __expf(-gv.w))) * uv.w;
            *reinterpret_cast<uint2*>(dh + 4 * j) =
                make_uint2(packh2(__float2half(h0v), __float2half(h1v)),
                           packh2(__float2half(h2v), __float2half(h3v)));
        }
        __threadfence();
        __syncthreads();
        if (tid == 0) atomicAdd(&g_done[mt_idx], 1);
    } else {
        // ---- consumer: gemm2 with scatter epilogue ----
        const int c = bid - NPROD;
        const int mt_idx = c % MTILES;
        const int m0 = mt_idx * BM;
        if (m0 >= g_off[NSEG]) return;
        const int n0 = (c / MTILES) * BN;
        int seg = 0;
#pragma unroll
        for (int s = 1; s < NSEG; s++) if (m0 >= g_off[s]) seg = s;

        if (tid == 0) {
            while (atomicAdd(&g_done[mt_idx], 0) < 16) { }
        }
        __syncthreads();
        __threadfence();

        const __half* gA = g_hh + (size_t)m0 * HS;
        const size_t wo = ((size_t)seg * DM + n0) * HS;
        const __half* B = g_wd + wo;

        float acc[2][8][4];
        gemm_mainloop(s2u(smem), gA, B, B + (size_t)64 * HS, tid, acc);

#pragma unroll
        for (int mt = 0; mt < 2; mt++) {
            const int rb = m0 + wm * 32 + mt * 16 + (lane >> 2);
            const int t0 = g_perm[rb];
            const int t1 = g_perm[rb + 8];
#pragma unroll
            for (int nt = 0; nt < 8; nt++) {
                const int cc = n0 + wn * 64 + nt * 8 + (lane & 3) * 2;
                if (t0 >= 0)
                    *reinterpret_cast<float2*>(out + (size_t)t0 * DM + cc) =
                        make_float2(acc[mt][nt][0], acc[mt][nt][1]);
                if (t1 >= 0)
                    *reinterpret_cast<float2*>(out + (size_t)t1 * DM + cc) =
                        make_float2(acc[mt][nt][2], acc[mt][nt][3]);
            }
        }
    }
}

// ---------------- entry point ----------------
extern "C" void kernel_launch(void* const* d_in, const int* in_sizes, int n_in,
                              void* d_out, int out_size)
{
    const float* x   = (const float*)d_in[0];
    const float* gw  = (const float*)d_in[1];
    const float* uw  = (const float*)d_in[2];
    const float* dw  = (const float*)d_in[3];
    const int*   idx = (const int*)d_in[4];
    float* out = (float*)d_out;

    static int smem_set = 0;
    if (!smem_set) {
        cudaFuncSetAttribute(gemm_fused, cudaFuncAttributeMaxDynamicSharedMemorySize, SMEM_G);
        smem_set = 1;
    }

    k_prep<<<(MAX_ROWS + 255) / 256, 256>>>();
    k_detect<<<(NT / 2 + 255) / 256, 256>>>(idx);
    k_count<<<(NT + 255) / 256, 256>>>(idx);
    k_off<<<1, 32>>>();
    k_scatter<<<(NT + 255) / 256, 256>>>(idx);

    k_convw<<<dim3(32, 32, 12), dim3(32, 8)>>>(gw, uw, dw);
    k_convx<<<(MAX_ROWS * (DM / 4) + 255) / 256, 256>>>(x);

    gemm_fused<<<NPROD + NCONS, NTHR, SMEM_G>>>(out);
}

// round 15
// speedup vs baseline: 1.1857x; 1.0490x over previous
#include <cuda_runtime.h>
#include <cuda_fp16.h>
#include <math.h>
#include <stdint.h>

// ---------------- problem constants ----------------
#define NT   16384
#define DM   1024
#define HS   1024
#define NSEG 4
#define KDIM 1024

#define BM   128
#define BN   128
#define BK   64
#define NKIT (KDIM / BK)        // 16
#define NTHR 256                // 8 warps: 4 wm x 2 wn, warp tile 32x64

#define MAX_ROWS (NT + NSEG * BM)   // 16896
#define MTILES   (MAX_ROWS / BM)    // 132
#define NPROD    (MTILES * 16)      // 2112 gemm1 CTAs (64 hidden cols each)
#define NCONS    (MTILES * 8)       // 1056 gemm2 CTAs

// SMEM stage: rows of 64 fp16 = 128B data, padded to 144B (conflict-free ldmatrix)
#define ROWB     144
#define TILEA    (128 * ROWB)       // 18432
#define TILEB    (128 * ROWB)       // 18432
#define STAGEB   (TILEA + TILEB)    // 36864
#define NSTAGE   3
#define SMEM_STG (NSTAGE * STAGEB)  // 110592
#define SMEM_TOT (SMEM_STG + 128 * 4)   // + perm tile; 111104 -> 2 CTAs/SM
#define EPI_STRIDE 132

// ---------------- device scratch ----------------
__device__ int g_perm[MAX_ROWS];
__device__ int g_off[NSEG + 1];
__device__ int g_done[MTILES];

__device__ __half g_xh[(size_t)NT * DM];         // activations fp16 (token order)
__device__ __half g_hh[(size_t)MAX_ROWS * HS];   // hidden fp16 (padded/permuted order)
// weights K-major [seg][n][k], fp16
__device__ __half g_wg[(size_t)NSEG * HS * DM];
__device__ __half g_wu[(size_t)NSEG * HS * DM];
__device__ __half g_wd[(size_t)NSEG * DM * HS];

// ---------------- small helpers ----------------
__device__ __forceinline__ uint32_t s2u(const void* p) {
    return (uint32_t)__cvta_generic_to_shared(p);
}
__device__ __forceinline__ void cpa16(uint32_t dst, const void* src) {
    asm volatile("cp.async.cg.shared.global [%0], [%1], 16;" :: "r"(dst), "l"(src));
}
#define CP_COMMIT() asm volatile("cp.async.commit_group;" ::: "memory")
#define CP_WAIT1()  asm volatile("cp.async.wait_group 1;" ::: "memory")
#define CP_WAIT0()  asm volatile("cp.async.wait_group 0;" ::: "memory")

__device__ __forceinline__ void ldmx4(uint32_t* r, uint32_t addr) {
    asm volatile("ldmatrix.sync.aligned.m8n8.x4.shared.b16 {%0,%1,%2,%3}, [%4];"
        : "=r"(r[0]), "=r"(r[1]), "=r"(r[2]), "=r"(r[3]) : "r"(addr));
}
__device__ __forceinline__ void mma16816(float* c, const uint32_t* a, const uint32_t* b) {
    asm volatile(
        "mma.sync.aligned.m16n8k16.row.col.f32.f16.f16.f32 "
        "{%0,%1,%2,%3}, {%4,%5,%6,%7}, {%8,%9}, {%0,%1,%2,%3};"
        : "+f"(c[0]), "+f"(c[1]), "+f"(c[2]), "+f"(c[3])
        : "r"(a[0]), "r"(a[1]), "r"(a[2]), "r"(a[3]), "r"(b[0]), "r"(b[1]));
}
__device__ __forceinline__ uint32_t packh2(__half a, __half b) {
    return ((uint32_t)__half_as_ushort(b) << 16) | __half_as_ushort(a);
}

// ---------------- routing: ONE single-CTA kernel ----------------
__global__ void k_route(const int* __restrict__ idx32) {
    __shared__ int scount[NSEG], scur[NSEG], soff[NSEG + 1];
    __shared__ int sdet;
    const int tid = threadIdx.x;

    if (tid < NSEG) { scount[tid] = 0; scur[tid] = 0; }
    if (tid == 0) sdet = 0;
    for (int i = tid; i < MTILES; i += 1024) g_done[i] = 0;
    for (int i = tid; i < MAX_ROWS; i += 1024) g_perm[i] = -1;
    __syncthreads();

    // dtype probe: odd 32-bit words all zero iff indices are int64
    int det = 0;
    for (int i = tid; i < NT / 2; i += 1024) det |= (idx32[2 * i + 1] != 0);
    if (det) sdet = 1;
    __syncthreads();
    const int is32 = sdet;

    for (int i = tid; i < NT; i += 1024)
        atomicAdd(&scount[(is32 ? idx32[i] : idx32[2 * i]) & (NSEG - 1)], 1);
    __syncthreads();

    if (tid == 0) {
        int o = 0;
        for (int s = 0; s < NSEG; s++) {
            soff[s] = o;
            g_off[s] = o;
            o += ((scount[s] + BM - 1) / BM) * BM;
        }
        soff[NSEG] = o;
        g_off[NSEG] = o;
    }
    __syncthreads();

    for (int i = tid; i < NT; i += 1024) {
        int s = (is32 ? idx32[i] : idx32[2 * i]) & (NSEG - 1);
        g_perm[soff[s] + atomicAdd(&scur[s], 1)] = i;
    }
}

// ---------------- conversion: x -> fp16, token order (no gather) ----------------
__global__ void k_convx(const float* __restrict__ x) {
    int gid = blockIdx.x * blockDim.x + threadIdx.x;
    if (gid >= NT * (DM / 4)) return;
    int r = gid >> 8;
    int c = (gid & 255) << 2;
    float4 v = *reinterpret_cast<const float4*>(x + (size_t)r * DM + c);
    size_t o = (size_t)r * DM + c;
    *reinterpret_cast<uint2*>(g_xh + o) =
        make_uint2(packh2(__float2half(v.x), __float2half(v.y)),
                   packh2(__float2half(v.z), __float2half(v.w)));
}

// ---------------- conversion: weights fp32 [k][n] -> fp16 [n][k] ----------------
__global__ void k_convw(const float* __restrict__ gw, const float* __restrict__ uw,
                        const float* __restrict__ dw) {
    __shared__ float tile[32][33];
    int mat = blockIdx.z >> 2, seg = blockIdx.z & 3;
    const float* W = (mat == 0 ? gw : (mat == 1 ? uw : dw)) + (size_t)seg * DM * HS;
    __half* O = (mat == 0 ? g_wg : (mat == 1 ? g_wu : g_wd)) + (size_t)seg * DM * HS;
    int n0 = blockIdx.x * 32, k0 = blockIdx.y * 32;
    int tx = threadIdx.x, ty = threadIdx.y;
#pragma unroll
    for (int i = 0; i < 4; i++)
        tile[ty + 8 * i][tx] = W[(size_t)(k0 + ty + 8 * i) * 1024 + n0 + tx];
    __syncthreads();
#pragma unroll
    for (int i = 0; i < 4; i++) {
        float v = tile[tx][ty + 8 * i];
        O[(size_t)(n0 + ty + 8 * i) * 1024 + k0 + tx] = __float2half(v);
    }
}

// ---------------- stage loaders (256 threads; 8 cp.async each) ----------------
// A gathered through sperm (producer) or contiguous (consumer).
// B panel: rows 0-63 from B0, rows 64-127 from B1 (B1 pre-offset by caller).
template<bool GATHER>
__device__ __forceinline__ void ld_stage(uint32_t sb,
        const __half* gA, const int* sperm,
        const __half* B0, const __half* B1,
        int kc, int tid) {
    const int ko = kc * BK;
#pragma unroll
    for (int q = 0; q < 4; q++) {               // A: 128 rows x 8 chunks
        int id = q * NTHR + tid;
        int row = id >> 3, c = id & 7;
        const __half* src = GATHER ? (gA + (size_t)sperm[row] * KDIM)
                                   : (gA + (size_t)row * KDIM);
        cpa16(sb + row * ROWB + c * 16, src + ko + c * 8);
    }
#pragma unroll
    for (int q = 0; q < 4; q++) {               // B: 128 rows x 8 chunks
        int id = q * NTHR + tid;
        int row = id >> 3, c = id & 7;
        const __half* src = (row < 64) ? B0 : (B1 - (size_t)64 * KDIM);
        cpa16(sb + TILEA + row * ROWB + c * 16, src + (size_t)row * KDIM + ko + c * 8);
    }
}

// ---------------- GEMM mainloop: CTA 128x128, 8 warps of 32x64, 3-stage ----------------
template<bool GATHER>
__device__ __forceinline__ void gemm_mainloop(uint32_t sbase,
        const __half* gA, const int* sperm,
        const __half* B0, const __half* B1,
        int tid, float acc[2][8][4]) {
    const int lane = tid & 31, wid = tid >> 5;
    const int wm = wid & 3, wn = wid >> 2;

#pragma unroll
    for (int i = 0; i < 2; i++)
#pragma unroll
        for (int j = 0; j < 8; j++)
#pragma unroll
            for (int q = 0; q < 4; q++) acc[i][j][q] = 0.f;

    ld_stage<GATHER>(sbase,          gA, sperm, B0, B1, 0, tid); CP_COMMIT();
    ld_stage<GATHER>(sbase + STAGEB, gA, sperm, B0, B1, 1, tid); CP_COMMIT();

    const int a_r  = lane & 15;
    const int a_kb = (lane >> 4) << 4;
    const int b_r  = ((lane >> 4) << 3) + (lane & 7);
    const int b_kb = ((lane >> 3) & 1) << 4;
    const int a_row0 = wm * 32;
    const int b_col0 = wn * 64;

    for (int it = 0; it < NKIT; it++) {
        if (it + 2 < NKIT) CP_WAIT1(); else CP_WAIT0();
        __syncthreads();
        if (it + 2 < NKIT) {
            ld_stage<GATHER>(sbase + ((it + 2) % NSTAGE) * STAGEB,
                             gA, sperm, B0, B1, it + 2, tid);
            CP_COMMIT();
        }
        const uint32_t sb = sbase + (it % NSTAGE) * STAGEB;
        const uint32_t sB = sb + TILEA;
#pragma unroll
        for (int ks = 0; ks < 4; ks++) {
            const int kb = ks * 32;
            uint32_t aH[2][4];
#pragma unroll
            for (int mt = 0; mt < 2; mt++) {
                uint32_t ad = sb + (a_row0 + mt * 16 + a_r) * ROWB + kb + a_kb;
                ldmx4(aH[mt], ad);
            }
#pragma unroll
            for (int nh = 0; nh < 2; nh++) {
                uint32_t bH[4][2];
#pragma unroll
                for (int p = 0; p < 2; p++) {
                    uint32_t bd = sB + (b_col0 + nh * 32 + p * 16 + b_r) * ROWB + kb + b_kb;
                    uint32_t r[4];
                    ldmx4(r, bd);
                    bH[2 * p][0] = r[0]; bH[2 * p][1] = r[1];
                    bH[2 * p + 1][0] = r[2]; bH[2 * p + 1][1] = r[3];
                }
#pragma unroll
                for (int mt = 0; mt < 2; mt++)
#pragma unroll
                    for (int q = 0; q < 4; q++)
                        mma16816(acc[mt][nh * 4 + q], aH[mt], bH[q]);
            }
        }
    }
}

// ---------------- fused GEMM kernel: producers (gemm1) + consumers (gemm2) ----------------
__global__ __launch_bounds__(NTHR, 2) void gemm_fused(float* __restrict__ out) {
    extern __shared__ char smem[];
    const int bid = blockIdx.x;
    const int tid = threadIdx.x, lane = tid & 31, wid = tid >> 5;
    const int wm = wid & 3, wn = wid >> 2;
    int* sperm = reinterpret_cast<int*>(smem + SMEM_STG);

    if (bid < NPROD) {
        // ---- producer: gemm1 [64 gate | 64 up] + fused SwiGLU ----
        const int mt_idx = bid >> 4;
        const int m0 = mt_idx * BM;
        if (m0 >= g_off[NSEG]) return;
        const int h0 = (bid & 15) * 64;
        int seg = 0;
#pragma unroll
        for (int s = 1; s < NSEG; s++) if (m0 >= g_off[s]) seg = s;

        // perm tile (pad rows -> token 0; their outputs are never scattered)
        if (tid < BM) {
            int t = g_perm[m0 + tid];
            sperm[tid] = t < 0 ? 0 : t;
        }
        __syncthreads();

        const size_t wo = ((size_t)seg * HS + h0) * DM;

        float acc[2][8][4];
        gemm_mainloop<true>(s2u(smem), g_xh, sperm, g_wg + wo, g_wu + wo, tid, acc);

        __syncthreads();
        float* S = reinterpret_cast<float*>(smem);
#pragma unroll
        for (int mt = 0; mt < 2; mt++) {
            const int r = wm * 32 + mt * 16 + (lane >> 2);
#pragma unroll
            for (int nt = 0; nt < 8; nt++) {
                const int c = wn * 64 + nt * 8 + (lane & 3) * 2;
                *reinterpret_cast<float2*>(S + (size_t)r * EPI_STRIDE + c) =
                    make_float2(acc[mt][nt][0], acc[mt][nt][1]);
                *reinterpret_cast<float2*>(S + (size_t)(r + 8) * EPI_STRIDE + c) =
                    make_float2(acc[mt][nt][2], acc[mt][nt][3]);
            }
        }
        __syncthreads();

        // swiglu -> fp16 hidden: cols 0-63 gate, 64-127 up; pair (c, c+64)
        const int row = tid >> 1, half = tid & 1;
        const float* Sg = S + (size_t)row * EPI_STRIDE + half * 32;
        const float* Su = Sg + 64;
        __half* dh = g_hh + (size_t)(m0 + row) * HS + h0 + half * 32;
#pragma unroll
        for (int j = 0; j < 8; j++) {
            float4 gv = *reinterpret_cast<const float4*>(Sg + 4 * j);
            float4 uv = *reinterpret_cast<const float4*>(Su + 4 * j);
            float h0v = (gv.x / (1.f + __expf(-gv.x))) * uv.x;
            float h1v = (gv.y / (1.f + __expf(-gv.y))) * uv.y;
            float h2v = (gv.z / (1.f + __expf(-gv.z))) * uv.z;
            float h3v = (gv.w / (1.f + __expf(-gv.w))) * uv.w;
            *reinterpret_cast<uint2*>(dh + 4 * j) =
                make_uint2(packh2(__float2half(h0v), __float2half(h1v)),
                           packh2(__float2half(h2v), __float2half(h3v)));
        }
        __threadfence();
        __syncthreads();
        if (tid == 0) atomicAdd(&g_done[mt_idx], 1);
    } else {
        // ---- consumer: gemm2 with scatter epilogue ----
        const int c = bid - NPROD;
        const int mt_idx = c % MTILES;
        const int m0 = mt_idx * BM;
        if (m0 >= g_off[NSEG]) return;
        const int n0 = (c / MTILES) * BN;
        int seg = 0;
#pragma unroll
        for (int s = 1; s < NSEG; s++) if (m0 >= g_off[s]) seg = s;

        if (tid == 0) {
            while (atomicAdd(&g_done[mt_idx], 0) < 16) { }
        }
        __syncthreads();
        __threadfence();

        const __half* gA = g_hh + (size_t)m0 * HS;
        const size_t wo = ((size_t)seg * DM + n0) * HS;
        const __half* B = g_wd + wo;

        float acc[2][8][4];
        gemm_mainloop<false>(s2u(smem), gA, nullptr, B, B + (size_t)64 * HS, tid, acc);

#pragma unroll
        for (int mt = 0; mt < 2; mt++) {
            const int rb = m0 + wm * 32 + mt * 16 + (lane >> 2);
            const int t0 = g_perm[rb];
            const int t1 = g_perm[rb + 8];
#pragma unroll
            for (int nt = 0; nt < 8; nt++) {
                const int cc = n0 + wn * 64 + nt * 8 + (lane & 3) * 2;
                if (t0 >= 0)
                    *reinterpret_cast<float2*>(out + (size_t)t0 * DM + cc) =
                        make_float2(acc[mt][nt][0], acc[mt][nt][1]);
                if (t1 >= 0)
                    *reinterpret_cast<float2*>(out + (size_t)t1 * DM + cc) =
                        make_float2(acc[mt][nt][2], acc[mt][nt][3]);
            }
        }
    }
}

// ---------------- entry point ----------------
extern "C" void kernel_launch(void* const* d_in, const int* in_sizes, int n_in,
                              void* d_out, int out_size)
{
    const float* x   = (const float*)d_in[0];
    const float* gw  = (const float*)d_in[1];
    const float* uw  = (const float*)d_in[2];
    const float* dw  = (const float*)d_in[3];
    const int*   idx = (const int*)d_in[4];
    float* out = (float*)d_out;

    static int smem_set = 0;
    if (!smem_set) {
        cudaFuncSetAttribute(gemm_fused, cudaFuncAttributeMaxDynamicSharedMemorySize, SMEM_TOT);
        smem_set = 1;
    }

    k_convw<<<dim3(32, 32, 12), dim3(32, 8)>>>(gw, uw, dw);
    k_convx<<<(NT * (DM / 4) + 255) / 256, 256>>>(x);
    k_route<<<1, 1024>>>(idx);
    gemm_fused<<<NPROD + NCONS, NTHR, SMEM_TOT>>>(out);
}

// round 16
// speedup vs baseline: 1.2276x; 1.0353x over previous
#include <cuda_runtime.h>
#include <cuda_fp16.h>
#include <math.h>
#include <stdint.h>

// ---------------- problem constants ----------------
#define NT   16384
#define DM   1024
#define HS   1024
#define NSEG 4
#define KDIM 1024

#define BM   128
#define BN   128
#define BK   64
#define NKIT (KDIM / BK)        // 16
#define NTHR 128                // 4 warps: 2 wm x 2 wn, warp tile 64x64

#define MAX_ROWS (NT + NSEG * BM)   // 16896
#define MTILES   (MAX_ROWS / BM)    // 132
#define NPROD    (MTILES * 16)      // 2112 gemm1 CTAs (64 hidden cols each)
#define NCONS    (MTILES * 8)       // 1056 gemm2 CTAs

// SMEM stage: rows of 64 fp16 = 128B data, padded to 144B (conflict-free ldmatrix)
#define ROWB     144
#define TILEA    (128 * ROWB)       // 18432
#define TILEB    (128 * ROWB)       // 18432
#define STAGEB   (TILEA + TILEB)    // 36864
#define NSTAGE   2
#define SMEM_STG (NSTAGE * STAGEB)  // 73728
#define SMEM_TOT (SMEM_STG + 128 * 4)   // + perm tile; 74240 -> 3 CTAs/SM
#define EPI_STRIDE 132

// ---------------- device scratch ----------------
__device__ int g_perm[MAX_ROWS];
__device__ int g_off[NSEG + 1];
__device__ int g_done[MTILES];

__device__ __half g_xh[(size_t)NT * DM];         // activations fp16 (token order)
__device__ __half g_hh[(size_t)MAX_ROWS * HS];   // hidden fp16 (padded/permuted order)
// weights K-major [seg][n][k], fp16
__device__ __half g_wg[(size_t)NSEG * HS * DM];
__device__ __half g_wu[(size_t)NSEG * HS * DM];
__device__ __half g_wd[(size_t)NSEG * DM * HS];

// ---------------- small helpers ----------------
__device__ __forceinline__ uint32_t s2u(const void* p) {
    return (uint32_t)__cvta_generic_to_shared(p);
}
__device__ __forceinline__ void cpa16(uint32_t dst, const void* src) {
    asm volatile("cp.async.cg.shared.global [%0], [%1], 16;" :: "r"(dst), "l"(src));
}
#define CP_COMMIT() asm volatile("cp.async.commit_group;" ::: "memory")
#define CP_WAIT0()  asm volatile("cp.async.wait_group 0;" ::: "memory")

__device__ __forceinline__ void ldmx4(uint32_t* r, uint32_t addr) {
    asm volatile("ldmatrix.sync.aligned.m8n8.x4.shared.b16 {%0,%1,%2,%3}, [%4];"
        : "=r"(r[0]), "=r"(r[1]), "=r"(r[2]), "=r"(r[3]) : "r"(addr));
}
__device__ __forceinline__ void mma16816(float* c, const uint32_t* a, const uint32_t* b) {
    asm volatile(
        "mma.sync.aligned.m16n8k16.row.col.f32.f16.f16.f32 "
        "{%0,%1,%2,%3}, {%4,%5,%6,%7}, {%8,%9}, {%0,%1,%2,%3};"
        : "+f"(c[0]), "+f"(c[1]), "+f"(c[2]), "+f"(c[3])
        : "r"(a[0]), "r"(a[1]), "r"(a[2]), "r"(a[3]), "r"(b[0]), "r"(b[1]));
}
__device__ __forceinline__ uint32_t packh2(__half a, __half b) {
    return ((uint32_t)__half_as_ushort(b) << 16) | __half_as_ushort(a);
}

// ---------------- routing: ONE single-CTA kernel ----------------
__global__ void k_route(const int* __restrict__ idx32) {
    __shared__ int scount[NSEG], scur[NSEG], soff[NSEG + 1];
    __shared__ int sdet;
    const int tid = threadIdx.x;

    if (tid < NSEG) { scount[tid] = 0; scur[tid] = 0; }
    if (tid == 0) sdet = 0;
    for (int i = tid; i < MTILES; i += 1024) g_done[i] = 0;
    for (int i = tid; i < MAX_ROWS; i += 1024) g_perm[i] = -1;
    __syncthreads();

    // dtype probe: odd 32-bit words all zero iff indices are int64
    int det = 0;
    for (int i = tid; i < NT / 2; i += 1024) det |= (idx32[2 * i + 1] != 0);
    if (det) sdet = 1;
    __syncthreads();
    const int is32 = sdet;

    for (int i = tid; i < NT; i += 1024)
        atomicAdd(&scount[(is32 ? idx32[i] : idx32[2 * i]) & (NSEG - 1)], 1);
    __syncthreads();

    if (tid == 0) {
        int o = 0;
        for (int s = 0; s < NSEG; s++) {
            soff[s] = o;
            g_off[s] = o;
            o += ((scount[s] + BM - 1) / BM) * BM;
        }
        soff[NSEG] = o;
        g_off[NSEG] = o;
    }
    __syncthreads();

    for (int i = tid; i < NT; i += 1024) {
        int s = (is32 ? idx32[i] : idx32[2 * i]) & (NSEG - 1);
        g_perm[soff[s] + atomicAdd(&scur[s], 1)] = i;
    }
}

// ---------------- conversion: x -> fp16, token order ----------------
__global__ void k_convx(const float* __restrict__ x) {
    int gid = blockIdx.x * blockDim.x + threadIdx.x;
    if (gid >= NT * (DM / 4)) return;
    int r = gid >> 8;
    int c = (gid & 255) << 2;
    float4 v = *reinterpret_cast<const float4*>(x + (size_t)r * DM + c);
    size_t o = (size_t)r * DM + c;
    *reinterpret_cast<uint2*>(g_xh + o) =
        make_uint2(packh2(__float2half(v.x), __float2half(v.y)),
                   packh2(__float2half(v.z), __float2half(v.w)));
}

// ---------------- conversion: weights fp32 [k][n] -> fp16 [n][k] ----------------
__global__ void k_convw(const float* __restrict__ gw, const float* __restrict__ uw,
                        const float* __restrict__ dw) {
    __shared__ float tile[32][33];
    int mat = blockIdx.z >> 2, seg = blockIdx.z & 3;
    const float* W = (mat == 0 ? gw : (mat == 1 ? uw : dw)) + (size_t)seg * DM * HS;
    __half* O = (mat == 0 ? g_wg : (mat == 1 ? g_wu : g_wd)) + (size_t)seg * DM * HS;
    int n0 = blockIdx.x * 32, k0 = blockIdx.y * 32;
    int tx = threadIdx.x, ty = threadIdx.y;
#pragma unroll
    for (int i = 0; i < 4; i++)
        tile[ty + 8 * i][tx] = W[(size_t)(k0 + ty + 8 * i) * 1024 + n0 + tx];
    __syncthreads();
#pragma unroll
    for (int i = 0; i < 4; i++) {
        float v = tile[tx][ty + 8 * i];
        O[(size_t)(n0 + ty + 8 * i) * 1024 + k0 + tx] = __float2half(v);
    }
}

// ---------------- stage loaders (128 threads; 16 cp.async each) ----------------
// A gathered through sperm (producer) or contiguous (consumer).
// B panel: rows 0-63 from B0, rows 64-127 from B1 (B1 pre-offset by caller).
template<bool GATHER>
__device__ __forceinline__ void ld_stage(uint32_t sb,
        const __half* gA, const int* sperm,
        const __half* B0, const __half* B1,
        int kc, int tid) {
    const int ko = kc * BK;
#pragma unroll
    for (int q = 0; q < 8; q++) {               // A: 128 rows x 8 chunks
        int id = q * NTHR + tid;
        int row = id >> 3, c = id & 7;
        const __half* src = GATHER ? (gA + (size_t)sperm[row] * KDIM)
                                   : (gA + (size_t)row * KDIM);
        cpa16(sb + row * ROWB + c * 16, src + ko + c * 8);
    }
#pragma unroll
    for (int q = 0; q < 8; q++) {               // B: 128 rows x 8 chunks
        int id = q * NTHR + tid;
        int row = id >> 3, c = id & 7;
        const __half* src = (row < 64) ? B0 : (B1 - (size_t)64 * KDIM);
        cpa16(sb + TILEA + row * ROWB + c * 16, src + (size_t)row * KDIM + ko + c * 8);
    }
}

// ---------------- GEMM mainloop: CTA 128x128, 4 warps of 64x64, 2-stage ----------------
template<bool GATHER>
__device__ __forceinline__ void gemm_mainloop(uint32_t sbase,
        const __half* gA, const int* sperm,
        const __half* B0, const __half* B1,
        int tid, float acc[4][8][4]) {
    const int lane = tid & 31, wid = tid >> 5;
    const int wm = wid & 1, wn = wid >> 1;

#pragma unroll
    for (int i = 0; i < 4; i++)
#pragma unroll
        for (int j = 0; j < 8; j++)
#pragma unroll
            for (int q = 0; q < 4; q++) acc[i][j][q] = 0.f;

    ld_stage<GATHER>(sbase, gA, sperm, B0, B1, 0, tid); CP_COMMIT();

    const int a_r  = lane & 15;
    const int a_kb = (lane >> 4) << 4;
    const int b_r  = ((lane >> 4) << 3) + (lane & 7);
    const int b_kb = ((lane >> 3) & 1) << 4;
    const int a_row0 = wm * 64;
    const int b_col0 = wn * 64;

    for (int it = 0; it < NKIT; it++) {
        CP_WAIT0();
        __syncthreads();
        if (it + 1 < NKIT) {
            ld_stage<GATHER>(sbase + ((it + 1) & 1) * STAGEB,
                             gA, sperm, B0, B1, it + 1, tid);
            CP_COMMIT();
        }
        const uint32_t sb = sbase + (it & 1) * STAGEB;
        const uint32_t sB = sb + TILEA;
#pragma unroll
        for (int ks = 0; ks < 4; ks++) {
            const int kb = ks * 32;
            uint32_t aH[4][4];
#pragma unroll
            for (int mt = 0; mt < 4; mt++) {
                uint32_t ad = sb + (a_row0 + mt * 16 + a_r) * ROWB + kb + a_kb;
                ldmx4(aH[mt], ad);
            }
#pragma unroll
            for (int nh = 0; nh < 2; nh++) {
                uint32_t bH[4][2];
#pragma unroll
                for (int p = 0; p < 2; p++) {
                    uint32_t bd = sB + (b_col0 + nh * 32 + p * 16 + b_r) * ROWB + kb + b_kb;
                    uint32_t r[4];
                    ldmx4(r, bd);
                    bH[2 * p][0] = r[0]; bH[2 * p][1] = r[1];
                    bH[2 * p + 1][0] = r[2]; bH[2 * p + 1][1] = r[3];
                }
#pragma unroll
                for (int mt = 0; mt < 4; mt++)
#pragma unroll
                    for (int q = 0; q < 4; q++)
                        mma16816(acc[mt][nh * 4 + q], aH[mt], bH[q]);
            }
        }
    }
}

// ---------------- fused GEMM kernel: producers (gemm1) + consumers (gemm2) ----------------
__global__ __launch_bounds__(NTHR, 3) void gemm_fused(float* __restrict__ out) {
    extern __shared__ char smem[];
    const int bid = blockIdx.x;
    const int tid = threadIdx.x, lane = tid & 31, wid = tid >> 5;
    const int wm = wid & 1, wn = wid >> 1;
    int* sperm = reinterpret_cast<int*>(smem + SMEM_STG);

    if (bid < NPROD) {
        // ---- producer: gemm1 [64 gate | 64 up] + fused SwiGLU ----
        const int mt_idx = bid >> 4;
        const int m0 = mt_idx * BM;
        if (m0 >= g_off[NSEG]) return;
        const int h0 = (bid & 15) * 64;
        int seg = 0;
#pragma unroll
        for (int s = 1; s < NSEG; s++) if (m0 >= g_off[s]) seg = s;

        // perm tile (pad rows -> token 0; their outputs are never scattered)
        sperm[tid] = max(g_perm[m0 + tid], 0);
        __syncthreads();

        const size_t wo = ((size_t)seg * HS + h0) * DM;

        float acc[4][8][4];
        gemm_mainloop<true>(s2u(smem), g_xh, sperm, g_wg + wo, g_wu + wo, tid, acc);

        __syncthreads();
        float* S = reinterpret_cast<float*>(smem);
#pragma unroll
        for (int mt = 0; mt < 4; mt++) {
            const int r = wm * 64 + mt * 16 + (lane >> 2);
#pragma unroll
            for (int nt = 0; nt < 8; nt++) {
                const int c = wn * 64 + nt * 8 + (lane & 3) * 2;
                *reinterpret_cast<float2*>(S + (size_t)r * EPI_STRIDE + c) =
                    make_float2(acc[mt][nt][0], acc[mt][nt][1]);
                *reinterpret_cast<float2*>(S + (size_t)(r + 8) * EPI_STRIDE + c) =
                    make_float2(acc[mt][nt][2], acc[mt][nt][3]);
            }
        }
        __syncthreads();

        // swiglu -> fp16 hidden: cols 0-63 gate, 64-127 up; one row per thread
        const int row = tid;
        const float* Sg = S + (size_t)row * EPI_STRIDE;
        const float* Su = Sg + 64;
        __half* dh = g_hh + (size_t)(m0 + row) * HS + h0;
#pragma unroll
        for (int j = 0; j < 16; j++) {
            float4 gv = *reinterpret_cast<const float4*>(Sg + 4 * j);
            float4 uv = *reinterpret_cast<const float4*>(Su + 4 * j);
            float h0v = (gv.x / (1.f + __expf(-gv.x))) * uv.x;
            float h1v = (gv.y / (1.f + __expf(-gv.y))) * uv.y;
            float h2v = (gv.z / (1.f + __expf(-gv.z))) * uv.z;
            float h3v = (gv.w / (1.f + __expf(-gv.w))) * uv.w;
            *reinterpret_cast<uint2*>(dh + 4 * j) =
                make_uint2(packh2(__float2half(h0v), __float2half(h1v)),
                           packh2(__float2half(h2v), __float2half(h3v)));
        }
        __threadfence();
        __syncthreads();
        if (tid == 0) atomicAdd(&g_done[mt_idx], 1);
    } else {
        // ---- consumer: gemm2 with scatter epilogue ----
        const int c = bid - NPROD;
        const int mt_idx = c % MTILES;
        const int m0 = mt_idx * BM;
        if (m0 >= g_off[NSEG]) return;
        const int n0 = (c / MTILES) * BN;
        int seg = 0;
#pragma unroll
        for (int s = 1; s < NSEG; s++) if (m0 >= g_off[s]) seg = s;

        if (tid == 0) {
            while (atomicAdd(&g_done[mt_idx], 0) < 16) { }
        }
        __syncthreads();
        __threadfence();

        const __half* gA = g_hh + (size_t)m0 * HS;
        const size_t wo = ((size_t)seg * DM + n0) * HS;
        const __half* B = g_wd + wo;

        float acc[4][8][4];
        gemm_mainloop<false>(s2u(smem), gA, nullptr, B, B + (size_t)64 * HS, tid, acc);

#pragma unroll
        for (int mt = 0; mt < 4; mt++) {
            const int rb = m0 + wm * 64 + mt * 16 + (lane >> 2);
            const int t0 = g_perm[rb];
            const int t1 = g_perm[rb + 8];
#pragma unroll
            for (int nt = 0; nt < 8; nt++) {
                const int cc = n0 + wn * 64 + nt * 8 + (lane & 3) * 2;
                if (t0 >= 0)
                    *reinterpret_cast<float2*>(out + (size_t)t0 * DM + cc) =
                        make_float2(acc[mt][nt][0], acc[mt][nt][1]);
                if (t1 >= 0)
                    *reinterpret_cast<float2*>(out + (size_t)t1 * DM + cc) =
                        make_float2(acc[mt][nt][2], acc[mt][nt][3]);
            }
        }
    }
}

// ---------------- entry point ----------------
extern "C" void kernel_launch(void* const* d_in, const int* in_sizes, int n_in,
                              void* d_out, int out_size)
{
    const float* x   = (const float*)d_in[0];
    const float* gw  = (const float*)d_in[1];
    const float* uw  = (const float*)d_in[2];
    const float* dw  = (const float*)d_in[3];
    const int*   idx = (const int*)d_in[4];
    float* out = (float*)d_out;

    static int smem_set = 0;
    if (!smem_set) {
        cudaFuncSetAttribute(gemm_fused, cudaFuncAttributeMaxDynamicSharedMemorySize, SMEM_TOT);
        smem_set = 1;
    }

    k_convw<<<dim3(32, 32, 12), dim3(32, 8)>>>(gw, uw, dw);
    k_convx<<<(NT * (DM / 4) + 255) / 256, 256>>>(x);
    k_route<<<1, 1024>>>(idx);
    gemm_fused<<<NPROD + NCONS, NTHR, SMEM_TOT>>>(out);
}